// round 7
// baseline (speedup 1.0000x reference)
#include <cuda_runtime.h>
#include <cstdint>
#include <math.h>

#define NBIN 65536
#define MAXB 16
#define NMAX 262144
#define TPB 512
#define NCTA 148
#define ZN (MAXB * NBIN / 4)   // uint4 count per histogram

// ---- gemv geometry (R6) ----
#define ROWB 1040                    // padded row: 260 words (16B-phase conflict-free)
#define XBUF (64 * ROWB)             // 66560
#define SW_OFF (2 * XBUF)            // 133120
#define SIDX_OFF (SW_OFF + 24576)    // 157696
#define SB_OFF (SIDX_OFF + 512)      // 158208
#define MBAR_OFF (SB_OFF + 96)       // 158304
#define SMEM_TOT 158336

// ---- device scratch (zero-init at load; every run restores zero state) ----
__device__ unsigned g_hist1[MAXB * NBIN];
__device__ unsigned g_hist2[MAXB * NBIN];
__device__ unsigned g_chunk1[MAXB * 256];
__device__ unsigned g_chunk2[MAXB * 256];
__device__ unsigned g_bucket1[MAXB];
__device__ unsigned g_rank1[MAXB];
__device__ unsigned g_kthkey[MAXB];
__device__ int g_list[NMAX];
__device__ int g_cnt;
__device__ unsigned g_bar[8];        // monotonic barrier counters (never reset)

__device__ __forceinline__ unsigned f2key(float s) {
    unsigned u = __float_as_uint(s);
    return (u & 0x80000000u) ? ~u : (u | 0x80000000u);
}
__device__ __forceinline__ unsigned long long ffma2(
    unsigned long long a, unsigned long long b, unsigned long long c) {
    unsigned long long d;
    asm("fma.rn.f32x2 %0, %1, %2, %3;" : "=l"(d) : "l"(a), "l"(b), "l"(c));
    return d;
}
__device__ __forceinline__ unsigned long long pack2(float x) {
    unsigned long long d;
    asm("mov.b64 %0, {%1, %1};" : "=l"(d) : "f"(x));
    return d;
}
__device__ __forceinline__ void unpack2(unsigned long long v, float& lo, float& hi) {
    asm("mov.b64 {%0, %1}, %2;" : "=f"(lo), "=f"(hi) : "l"(v));
}
__device__ __forceinline__ float getc(const float4& v, int s) {
    return (s == 0) ? v.x : (s == 1) ? v.y : (s == 2) ? v.z : v.w;
}
__device__ __forceinline__ uint32_t s2u(const void* p) {
    uint32_t a;
    asm("{ .reg .u64 t; cvta.to.shared.u64 t, %1; cvt.u32.u64 %0, t; }"
        : "=r"(a) : "l"(p));
    return a;
}
__device__ __forceinline__ void mbar_init(uint32_t mbar, uint32_t cnt) {
    asm volatile("mbarrier.init.shared.b64 [%0], %1;" :: "r"(mbar), "r"(cnt) : "memory");
}
__device__ __forceinline__ void mbar_expect(uint32_t mbar, uint32_t bytes) {
    asm volatile("mbarrier.arrive.expect_tx.shared.b64 _, [%0], %1;"
                 :: "r"(mbar), "r"(bytes) : "memory");
}
__device__ __forceinline__ void mbar_wait(uint32_t mbar, uint32_t parity) {
    asm volatile(
        "{\n\t.reg .pred P;\n"
        "WL_%=:\n\t"
        "mbarrier.try_wait.parity.acquire.cta.shared::cta.b64 P, [%0], %1, 0x989680;\n\t"
        "@P bra.uni WD_%=;\n\t"
        "bra.uni WL_%=;\n"
        "WD_%=:\n\t}"
        :: "r"(mbar), "r"(parity) : "memory");
}
__device__ __forceinline__ void bulk_copy(uint32_t dst, const void* src,
                                          uint32_t bytes, uint32_t mbar) {
    asm volatile(
        "cp.async.bulk.shared::cluster.global.mbarrier::complete_tx::bytes "
        "[%0], [%1], %2, [%3];"
        :: "r"(dst), "l"(src), "r"(bytes), "r"(mbar) : "memory");
}

// Reset-free grid barrier: counter grows by NCTA per use; release target is the
// next multiple of NCTA. Wrap-safe signed compare. All 148 CTAs co-resident.
__device__ __forceinline__ void gbar(int i) {
    __syncthreads();
    if (threadIdx.x == 0) {
        __threadfence();
        unsigned old = atomicAdd(&g_bar[i], 1u);
        unsigned target = old - (old % NCTA) + NCTA;
        unsigned cur;
        do {
            asm volatile("ld.acquire.gpu.global.u32 %0, [%1];"
                         : "=r"(cur) : "l"(&g_bar[i]) : "memory");
        } while ((int)(cur - target) < 0);
    }
    __syncthreads();
}

// One CTA handles one batch; threads 0..255 active. Two shfl suffix scans.
__device__ void scan_phase(int level, int b, unsigned target) {
    const unsigned* h  = (level == 1 ? g_hist1  : g_hist2)  + (size_t)b * NBIN;
    const unsigned* ch = (level == 1 ? g_chunk1 : g_chunk2) + (size_t)b * 256;

    __shared__ unsigned wsum[8];
    __shared__ int s_sel;
    __shared__ unsigned s_rem;

    int t = threadIdx.x, lane = t & 31, w = t >> 5;
    unsigned v = 0, x = 0;

    if (t < 256) {
        v = ch[t];
        x = v;
#pragma unroll
        for (int off = 1; off < 32; off <<= 1) {
            unsigned nv = __shfl_down_sync(0xffffffffu, x, off);
            if (lane + off < 32) x += nv;
        }
        if (lane == 0) wsum[w] = x;
    }
    __syncthreads();
    if (t < 256) {
        unsigned add = 0;
        for (int w2 = w + 1; w2 < 8; w2++) add += wsum[w2];
        unsigned s = x + add;
        if (s >= target && s - v < target) { s_sel = t; s_rem = target - (s - v); }
    }
    __syncthreads();
    int sel = s_sel;
    unsigned rem = s_rem;
    __syncthreads();

    if (t < 256) {
        v = h[sel * 256 + t];
        x = v;
#pragma unroll
        for (int off = 1; off < 32; off <<= 1) {
            unsigned nv = __shfl_down_sync(0xffffffffu, x, off);
            if (lane + off < 32) x += nv;
        }
        if (lane == 0) wsum[w] = x;
    }
    __syncthreads();
    if (t < 256) {
        unsigned add = 0;
        for (int w2 = w + 1; w2 < 8; w2++) add += wsum[w2];
        unsigned s = x + add;
        if (s >= rem && s - v < rem) {
            unsigned bin = (unsigned)(sel * 256 + t);
            if (level == 1) {
                g_bucket1[b] = bin;
                g_rank1[b] = rem - (s - v);
            } else {
                g_kthkey[b] = (g_bucket1[b] << 16) | bin;
            }
        }
    }
}

__global__ void __launch_bounds__(TPB, 1) mega_kernel(
    const float* __restrict__ feats,
    const float* __restrict__ scores,
    const int* __restrict__ bids,
    const float* __restrict__ w_reg,
    const float* __restrict__ w_cls,
    const float* __restrict__ b_cls,
    const float* __restrict__ scale,
    const int* __restrict__ nb_ptr,
    const int* __restrict__ k_ptr,
    float* __restrict__ out, int N) {
    extern __shared__ char smem[];
    int t = threadIdx.x;
    int bid = blockIdx.x;
    int gid = bid * TPB + t;
    const int GSTRIDE = NCTA * TPB;

    int B = nb_ptr ? *nb_ptr : 8;
    if (B < 1 || B > MAXB) B = 8;
    unsigned K = (unsigned)(k_ptr ? *k_ptr : 8192);

    uint32_t mb0 = s2u(smem + MBAR_OFF);
    uint32_t mb1 = mb0 + 8;
    if (t < 2) mbar_init(t == 0 ? mb0 : mb1, 1);

    // ---- phase 1: hist1 + chunk1 ----
    for (int i = gid; i < N; i += GSTRIDE) {
        unsigned b = (unsigned)bids[i];
        if (b < (unsigned)MAXB) {
            unsigned key = f2key(scores[i]);
            atomicAdd(&g_hist1[b * NBIN + (key >> 16)], 1u);
            atomicAdd(&g_chunk1[b * 256 + (key >> 24)], 1u);
        }
    }
    gbar(0);

    // ---- phase 2: scan level 1 ----
    if (bid < B) scan_phase(1, bid, K);
    gbar(1);

    // ---- phase 3: hist2 + chunk2; zero L1 state ----
    {
        uint4 z = make_uint4(0u, 0u, 0u, 0u);
        uint4* h14 = reinterpret_cast<uint4*>(g_hist1);
        for (int i = gid; i < ZN; i += GSTRIDE) h14[i] = z;
        for (int i = gid; i < MAXB * 256; i += GSTRIDE) g_chunk1[i] = 0u;
        for (int i = gid; i < N; i += GSTRIDE) {
            unsigned b = (unsigned)bids[i];
            if (b < (unsigned)MAXB) {
                unsigned key = f2key(scores[i]);
                if ((key >> 16) == g_bucket1[b]) {
                    atomicAdd(&g_hist2[b * NBIN + (key & 0xFFFFu)], 1u);
                    atomicAdd(&g_chunk2[b * 256 + ((key >> 8) & 0xFFu)], 1u);
                }
            }
        }
    }
    gbar(2);

    // ---- phase 4: scan level 2 -> kthkey; reset g_cnt ----
    if (bid == 0 && t == 0) g_cnt = 0;
    if (bid < B) scan_phase(2, bid, g_rank1[bid]);
    gbar(3);

    // ---- phase 5: compact + fill pruned rows; zero L2 state ----
    {
        __shared__ float sbq[24];
        __shared__ unsigned skey[MAXB];
        if (t < MAXB) skey[t] = g_kthkey[t];
        if (t < 24) sbq[t] = (t < 6) ? 1.0f : b_cls[t - 6];
        __syncthreads();

        uint4 z = make_uint4(0u, 0u, 0u, 0u);
        uint4* h24 = reinterpret_cast<uint4*>(g_hist2);
        for (int i = gid; i < ZN; i += GSTRIDE) h24[i] = z;
        for (int i = gid; i < MAXB * 256; i += GSTRIDE) g_chunk2[i] = 0u;

        float4* out4 = (float4*)out;
        int iters = (N + GSTRIDE - 1) / GSTRIDE;
        for (int it = 0; it < iters; it++) {
            int p = gid + it * GSTRIDE;
            bool keep = false;
            if (p < N) {
                unsigned b = (unsigned)bids[p];
                unsigned key = f2key(scores[p]);
                keep = (b < (unsigned)MAXB) && (key >= skey[b]);
                if (!keep) {
                    float4* o = out4 + (size_t)p * 6;
                    o[0] = make_float4(1.f, 1.f, 1.f, 1.f);
                    o[1] = make_float4(1.f, 1.f, sbq[6], sbq[7]);
                    o[2] = make_float4(sbq[8], sbq[9], sbq[10], sbq[11]);
                    o[3] = make_float4(sbq[12], sbq[13], sbq[14], sbq[15]);
                    o[4] = make_float4(sbq[16], sbq[17], sbq[18], sbq[19]);
                    o[5] = make_float4(sbq[20], sbq[21], sbq[22], sbq[23]);
                }
            }
            unsigned bal = __ballot_sync(0xffffffffu, keep);
            int nk = __popc(bal);
            if (nk) {
                int gb = 0;
                if ((t & 31) == 0) gb = atomicAdd(&g_cnt, nk);
                gb = __shfl_sync(0xffffffffu, gb, 0);
                if (keep) g_list[gb + __popc(bal & ((1u << (t & 31)) - 1u))] = p;
            }
        }
    }
    gbar(4);

    // ---- phase 6: staged split-K GEMV (R6 design) ----
    {
        float* sw = (float*)(smem + SW_OFF);    // [256][24]
        int* sidx = (int*)(smem + SIDX_OFF);    // [2][64]
        float* sb = (float*)(smem + SB_OFF);

        if (t < 24) sb[t] = (t < 6) ? 1.0f : b_cls[t - 6];
        for (int i = t; i < 6144; i += TPB) {
            int k = i / 24, j = i % 24;
            sw[i] = (j < 6) ? w_reg[k * 6 + j] : w_cls[k * 18 + (j - 6)];
        }
        float sc = scale[0];
        int T = g_cnt;
        int ntiles = (T + 63) >> 6;
        __syncthreads();

        int tile = bid;
        int ph0 = 0, ph1 = 0;

        if (tile < ntiles) {
            int nv = min(64, T - (tile << 6));
            if (t < 64) sidx[t] = (t < nv) ? g_list[(tile << 6) + t] : 0;
            if (t == 0) mbar_expect(mb0, (unsigned)nv << 10);
        }
        __syncthreads();
        if (tile < ntiles && t < min(64, T - (tile << 6)))
            bulk_copy(s2u(smem) + t * ROWB, feats + (size_t)sidx[t] * 256, 1024, mb0);

        const ulonglong2* swp = (const ulonglong2*)sw;
        int b = 0;
        for (; tile < ntiles; tile += NCTA, b ^= 1) {
            int nv = min(64, T - (tile << 6));
            int nxt = tile + NCTA;
            int bn = b ^ 1;
            uint32_t mbn = bn ? mb1 : mb0;

            if (nxt < ntiles) {
                int nv2 = min(64, T - (nxt << 6));
                if (t < 64) sidx[bn * 64 + t] = (t < nv2) ? g_list[(nxt << 6) + t] : 0;
                if (t == 0) mbar_expect(mbn, (unsigned)nv2 << 10);
            }
            __syncthreads();
            if (nxt < ntiles) {
                int nv2 = min(64, T - (nxt << 6));
                if (t < nv2)
                    bulk_copy(s2u(smem) + bn * XBUF + t * ROWB,
                              feats + (size_t)sidx[bn * 64 + t] * 256, 1024, mbn);
            }

            if (b == 0) { mbar_wait(mb0, ph0); ph0 ^= 1; }
            else        { mbar_wait(mb1, ph1); ph1 ^= 1; }

            int p = t & 63, q = t >> 6;
            const float4* xrow = (const float4*)(smem + b * XBUF + p * ROWB) + q * 8;
            unsigned long long acc[12];
#pragma unroll
            for (int j = 0; j < 12; j++) acc[j] = 0ull;
#pragma unroll
            for (int c4 = 0; c4 < 8; c4++) {
                float4 xv = xrow[c4];
#pragma unroll
                for (int s = 0; s < 4; s++) {
                    int k = (q << 5) + (c4 << 2) + s;
                    unsigned long long x2 = pack2(getc(xv, s));
#pragma unroll
                    for (int j = 0; j < 6; j++) {
                        ulonglong2 wv = swp[k * 6 + j];
                        acc[2 * j]     = ffma2(x2, wv.x, acc[2 * j]);
                        acc[2 * j + 1] = ffma2(x2, wv.y, acc[2 * j + 1]);
                    }
                }
            }
            __syncthreads();  // x reads done; reuse buf b as reduction scratch

            {
                ulonglong2* rb = (ulonglong2*)(smem + b * XBUF + ((q << 6) + p) * 112);
#pragma unroll
                for (int j = 0; j < 6; j++)
                    rb[j] = make_ulonglong2(acc[2 * j], acc[2 * j + 1]);
            }
            __syncthreads();

            for (int s = t; s < 768; s += TPB) {
                int p2 = s & 63, j = s >> 6;
                float lo = 0.f, hi = 0.f;
#pragma unroll
                for (int q2 = 0; q2 < 8; q2++) {
                    unsigned long long pv = *(const unsigned long long*)(
                        smem + b * XBUF + ((q2 << 6) + p2) * 112 + j * 8);
                    float a, bb;
                    unpack2(pv, a, bb);
                    lo += a; hi += bb;
                }
                if (p2 < nv) {
                    int col = j << 1;
                    float2 o;
                    if (col < 6) { o.x = __expf(sc * lo); o.y = __expf(sc * hi); }
                    else         { o.x = lo + sb[col];    o.y = hi + sb[col + 1]; }
                    *(float2*)(out + (size_t)sidx[b * 64 + p2] * 24 + col) = o;
                }
            }
            __syncthreads();
        }
    }
}

extern "C" void kernel_launch(void* const* d_in, const int* in_sizes, int n_in,
                              void* d_out, int out_size) {
    const float* feats  = (const float*)d_in[0];
    const float* scores = (const float*)d_in[1];
    const float* w_reg  = (const float*)d_in[2];
    const float* w_cls  = (const float*)d_in[3];
    const float* b_cls  = (const float*)d_in[4];
    const float* scale  = (const float*)d_in[5];
    const int*   bids   = (const int*)d_in[6];
    const int*   nb     = (n_in > 7) ? (const int*)d_in[7] : nullptr;
    const int*   kp     = (n_in > 8) ? (const int*)d_in[8] : nullptr;
    int N = in_sizes[0] / 256;

    static bool attr_set = false;
    if (!attr_set) {
        cudaFuncSetAttribute(mega_kernel,
                             cudaFuncAttributeMaxDynamicSharedMemorySize, SMEM_TOT);
        attr_set = true;
    }

    mega_kernel<<<NCTA, TPB, SMEM_TOT>>>(feats, scores, bids, w_reg, w_cls,
                                         b_cls, scale, nb, kp,
                                         (float*)d_out, N);
}

// round 8
// speedup vs baseline: 1.1013x; 1.1013x over previous
#include <cuda_runtime.h>
#include <cstdint>
#include <math.h>

#define NBIN 65536
#define MAXB 16
#define NMAX 262144
#define ZN (MAXB * NBIN / 4)

#define SEL_TPB 1024
#define SEL_NCTA 296

#define GE_TPB 512
#define GE_NCTA 148
#define ROWB 1040                    // 260 words (=4 mod 32 banks): conflict-free x loads
#define XBUF (64 * ROWB)             // 66560
#define SLOT 208                     // 52 words: conflict-free partial stores
#define SW_OFF (2 * XBUF)            // 133120
#define SIDX_OFF (SW_OFF + 24576)    // 157696
#define SB_OFF (SIDX_OFF + 512)      // 158208
#define MBAR_OFF (SB_OFF + 96)       // 158304
#define SMEM_TOT (MBAR_OFF + 32)

// ---- device scratch (zero-init; every run restores zero state) ----
__device__ unsigned g_hist1[MAXB * NBIN];
__device__ unsigned g_hist2[MAXB * NBIN];
__device__ unsigned g_chunk1[MAXB * 256];
__device__ unsigned g_chunk2[MAXB * 256];
__device__ unsigned g_bucket1[MAXB];
__device__ unsigned g_rank1[MAXB];
__device__ unsigned g_kthkey[MAXB];
__device__ int g_list[NMAX];
__device__ int g_cnt;
__device__ unsigned g_bar[8];        // monotonic barrier counters (never reset)

__device__ __forceinline__ unsigned f2key(float s) {
    unsigned u = __float_as_uint(s);
    return (u & 0x80000000u) ? ~u : (u | 0x80000000u);
}
__device__ __forceinline__ unsigned long long ffma2(
    unsigned long long a, unsigned long long b, unsigned long long c) {
    unsigned long long d;
    asm("fma.rn.f32x2 %0, %1, %2, %3;" : "=l"(d) : "l"(a), "l"(b), "l"(c));
    return d;
}
__device__ __forceinline__ unsigned long long addf2(
    unsigned long long a, unsigned long long b) {
    unsigned long long d;
    asm("add.rn.f32x2 %0, %1, %2;" : "=l"(d) : "l"(a), "l"(b));
    return d;
}
__device__ __forceinline__ unsigned long long pack2(float x) {
    unsigned long long d;
    asm("mov.b64 %0, {%1, %1};" : "=l"(d) : "f"(x));
    return d;
}
__device__ __forceinline__ void unpack2(unsigned long long v, float& lo, float& hi) {
    asm("mov.b64 {%0, %1}, %2;" : "=f"(lo), "=f"(hi) : "l"(v));
}
__device__ __forceinline__ float getc(const float4& v, int s) {
    return (s == 0) ? v.x : (s == 1) ? v.y : (s == 2) ? v.z : v.w;
}
__device__ __forceinline__ uint32_t s2u(const void* p) {
    uint32_t a;
    asm("{ .reg .u64 t; cvta.to.shared.u64 t, %1; cvt.u32.u64 %0, t; }"
        : "=r"(a) : "l"(p));
    return a;
}
__device__ __forceinline__ void mbar_init(uint32_t mbar, uint32_t cnt) {
    asm volatile("mbarrier.init.shared.b64 [%0], %1;" :: "r"(mbar), "r"(cnt) : "memory");
}
__device__ __forceinline__ void mbar_expect(uint32_t mbar, uint32_t bytes) {
    asm volatile("mbarrier.arrive.expect_tx.shared.b64 _, [%0], %1;"
                 :: "r"(mbar), "r"(bytes) : "memory");
}
__device__ __forceinline__ void mbar_wait(uint32_t mbar, uint32_t parity) {
    asm volatile(
        "{\n\t.reg .pred P;\n"
        "WL_%=:\n\t"
        "mbarrier.try_wait.parity.acquire.cta.shared::cta.b64 P, [%0], %1, 0x989680;\n\t"
        "@P bra.uni WD_%=;\n\t"
        "bra.uni WL_%=;\n"
        "WD_%=:\n\t}"
        :: "r"(mbar), "r"(parity) : "memory");
}
__device__ __forceinline__ void bulk_copy(uint32_t dst, const void* src,
                                          uint32_t bytes, uint32_t mbar) {
    asm volatile(
        "cp.async.bulk.shared::cluster.global.mbarrier::complete_tx::bytes "
        "[%0], [%1], %2, [%3];"
        :: "r"(dst), "l"(src), "r"(bytes), "r"(mbar) : "memory");
}

// Reset-free grid barrier (SEL_NCTA CTAs, all co-resident at occ 2).
__device__ __forceinline__ void gbar(int i) {
    __syncthreads();
    if (threadIdx.x == 0) {
        __threadfence();
        unsigned old = atomicAdd(&g_bar[i], 1u);
        unsigned target = old - (old % SEL_NCTA) + SEL_NCTA;
        unsigned cur;
        do {
            asm volatile("ld.acquire.gpu.global.u32 %0, [%1];"
                         : "=r"(cur) : "l"(&g_bar[i]) : "memory");
        } while ((int)(cur - target) < 0);
    }
    __syncthreads();
}

// CTA b handles batch b; threads 0..255 active; two shfl suffix scans.
__device__ void scan_phase(int level, int b, unsigned target,
                           unsigned* wsum, int* s_sel, unsigned* s_rem) {
    const unsigned* h  = (level == 1 ? g_hist1  : g_hist2)  + (size_t)b * NBIN;
    const unsigned* ch = (level == 1 ? g_chunk1 : g_chunk2) + (size_t)b * 256;

    int t = threadIdx.x, lane = t & 31, w = t >> 5;
    unsigned v = 0, x = 0;

    if (t < 256) {
        v = ch[t];
        x = v;
#pragma unroll
        for (int off = 1; off < 32; off <<= 1) {
            unsigned nv = __shfl_down_sync(0xffffffffu, x, off);
            if (lane + off < 32) x += nv;
        }
        if (lane == 0) wsum[w] = x;
    }
    __syncthreads();
    if (t < 256) {
        unsigned add = 0;
        for (int w2 = w + 1; w2 < 8; w2++) add += wsum[w2];
        unsigned s = x + add;
        if (s >= target && s - v < target) { *s_sel = t; *s_rem = target - (s - v); }
    }
    __syncthreads();
    int sel = *s_sel;
    unsigned rem = *s_rem;
    __syncthreads();

    if (t < 256) {
        v = h[sel * 256 + t];
        x = v;
#pragma unroll
        for (int off = 1; off < 32; off <<= 1) {
            unsigned nv = __shfl_down_sync(0xffffffffu, x, off);
            if (lane + off < 32) x += nv;
        }
        if (lane == 0) wsum[w] = x;
    }
    __syncthreads();
    if (t < 256) {
        unsigned add = 0;
        for (int w2 = w + 1; w2 < 8; w2++) add += wsum[w2];
        unsigned s = x + add;
        if (s >= rem && s - v < rem) {
            unsigned bin = (unsigned)(sel * 256 + t);
            if (level == 1) {
                g_bucket1[b] = bin;
                g_rank1[b] = rem - (s - v);
            } else {
                g_kthkey[b] = (g_bucket1[b] << 16) | bin;
            }
        }
    }
}

// Fused selection: hist1 -> scan1 -> hist2 -> scan2 -> compact/fill.
__global__ void __launch_bounds__(SEL_TPB, 2) sel_kernel(
    const float* __restrict__ scores,
    const int* __restrict__ bids,
    const float* __restrict__ b_cls,
    const int* __restrict__ nb_ptr,
    const int* __restrict__ k_ptr,
    float4* __restrict__ out4, int N) {
    __shared__ unsigned wsum[8];
    __shared__ int s_sel;
    __shared__ unsigned s_rem;
    __shared__ float sbq[24];
    __shared__ unsigned skey[MAXB];

    int t = threadIdx.x;
    int bid = blockIdx.x;
    int gid = bid * SEL_TPB + t;

    int B = nb_ptr ? *nb_ptr : 8;
    if (B < 1 || B > MAXB) B = 8;
    unsigned K = (unsigned)(k_ptr ? *k_ptr : 8192);

    // P1: hist1 + chunk1
    if (gid < N) {
        unsigned b = (unsigned)bids[gid];
        if (b < (unsigned)MAXB) {
            unsigned key = f2key(scores[gid]);
            atomicAdd(&g_hist1[b * NBIN + (key >> 16)], 1u);
            atomicAdd(&g_chunk1[b * 256 + (key >> 24)], 1u);
        }
    }
    gbar(0);

    // P2: scan level 1
    if (bid < B) scan_phase(1, bid, K, wsum, &s_sel, &s_rem);
    gbar(1);

    // P3: hist2 + chunk2; zero level-1 state
    if (gid < ZN) reinterpret_cast<uint4*>(g_hist1)[gid] = make_uint4(0u, 0u, 0u, 0u);
    if (gid < MAXB * 256) g_chunk1[gid] = 0u;
    if (gid < N) {
        unsigned b = (unsigned)bids[gid];
        if (b < (unsigned)MAXB) {
            unsigned key = f2key(scores[gid]);
            if ((key >> 16) == g_bucket1[b]) {
                atomicAdd(&g_hist2[b * NBIN + (key & 0xFFFFu)], 1u);
                atomicAdd(&g_chunk2[b * 256 + ((key >> 8) & 0xFFu)], 1u);
            }
        }
    }
    gbar(2);

    // P4: scan level 2 + reset g_cnt
    if (bid == 0 && t == 0) g_cnt = 0;
    if (bid < B) scan_phase(2, bid, g_rank1[bid], wsum, &s_sel, &s_rem);
    gbar(3);

    // P5: compact + fill; zero level-2 state
    if (t < MAXB) skey[t] = g_kthkey[t];
    if (t < 24) sbq[t] = (t < 6) ? 1.0f : b_cls[t - 6];
    __syncthreads();

    if (gid < ZN) reinterpret_cast<uint4*>(g_hist2)[gid] = make_uint4(0u, 0u, 0u, 0u);
    if (gid < MAXB * 256) g_chunk2[gid] = 0u;

    bool keep = false;
    if (gid < N) {
        unsigned b = (unsigned)bids[gid];
        unsigned key = f2key(scores[gid]);
        keep = (b < (unsigned)MAXB) && (key >= skey[b]);
        if (!keep) {
            float4* o = out4 + (size_t)gid * 6;
            o[0] = make_float4(1.f, 1.f, 1.f, 1.f);
            o[1] = make_float4(1.f, 1.f, sbq[6], sbq[7]);
            o[2] = make_float4(sbq[8], sbq[9], sbq[10], sbq[11]);
            o[3] = make_float4(sbq[12], sbq[13], sbq[14], sbq[15]);
            o[4] = make_float4(sbq[16], sbq[17], sbq[18], sbq[19]);
            o[5] = make_float4(sbq[20], sbq[21], sbq[22], sbq[23]);
        }
    }
    unsigned bal = __ballot_sync(0xffffffffu, keep);
    int nk = __popc(bal);
    if (nk) {
        int gb = 0;
        if ((t & 31) == 0) gb = atomicAdd(&g_cnt, nk);
        gb = __shfl_sync(0xffffffffu, gb, 0);
        if (keep) g_list[gb + __popc(bal & ((1u << (t & 31)) - 1u))] = gid;
    }
}

// Staged GEMV: tile=64 pts, 512 thr. lane l owns pts (l, l+32); warp q owns
// k-slice [16q,16q+16). Double-buffered cp.async.bulk; 2-phase smem K-fold.
__global__ void __launch_bounds__(GE_TPB, 1) gemv_kernel(
    const float* __restrict__ feats,
    const float* __restrict__ w_reg,
    const float* __restrict__ w_cls,
    const float* __restrict__ b_cls,
    const float* __restrict__ scale,
    float* __restrict__ out) {
    extern __shared__ char smem[];
    float* sw = (float*)(smem + SW_OFF);    // [256][24]
    int* sidx = (int*)(smem + SIDX_OFF);    // [2][64]
    float* sb = (float*)(smem + SB_OFF);
    uint32_t mb0 = s2u(smem + MBAR_OFF);
    uint32_t mb1 = mb0 + 8;

    int t = threadIdx.x;
    int l = t & 31, q = t >> 5;             // q in [0,16)

    if (t < 24) sb[t] = (t < 6) ? 1.0f : b_cls[t - 6];
    for (int i = t; i < 6144; i += GE_TPB) {
        int k = i / 24, j = i % 24;
        sw[i] = (j < 6) ? w_reg[k * 6 + j] : w_cls[k * 18 + (j - 6)];
    }
    if (t < 2) mbar_init(t == 0 ? mb0 : mb1, 1);
    float sc = scale[0];
    int T = g_cnt;
    int ntiles = (T + 63) >> 6;
    __syncthreads();

    int tile = blockIdx.x;
    int ph0 = 0, ph1 = 0;

    if (tile < ntiles) {
        int nv = min(64, T - (tile << 6));
        if (t < 64) sidx[t] = (t < nv) ? g_list[(tile << 6) + t] : 0;
        if (t == 0) mbar_expect(mb0, (unsigned)nv << 10);
    }
    __syncthreads();
    if (tile < ntiles && t < min(64, T - (tile << 6)))
        bulk_copy(s2u(smem) + t * ROWB, feats + (size_t)sidx[t] * 256, 1024, mb0);

    const ulonglong2* swp = (const ulonglong2*)sw;  // 6 per k
    int b = 0;
    for (; tile < ntiles; tile += GE_NCTA, b ^= 1) {
        int nv = min(64, T - (tile << 6));
        int nxt = tile + GE_NCTA;
        int bn = b ^ 1;
        uint32_t mbn = bn ? mb1 : mb0;

        if (nxt < ntiles) {
            int nv2 = min(64, T - (nxt << 6));
            if (t < 64) sidx[bn * 64 + t] = (t < nv2) ? g_list[(nxt << 6) + t] : 0;
            if (t == 0) mbar_expect(mbn, (unsigned)nv2 << 10);
        }
        __syncthreads();
        if (nxt < ntiles) {
            int nv2 = min(64, T - (nxt << 6));
            if (t < nv2)
                bulk_copy(s2u(smem) + bn * XBUF + t * ROWB,
                          feats + (size_t)sidx[bn * 64 + t] * 256, 1024, mbn);
        }

        if (b == 0) { mbar_wait(mb0, ph0); ph0 ^= 1; }
        else        { mbar_wait(mb1, ph1); ph1 ^= 1; }

        // compute: 2 points (l, l+32), k-slice [16q, 16q+16)
        const float4* x0 = (const float4*)(smem + b * XBUF + l * ROWB) + q * 4;
        const float4* x1 = (const float4*)(smem + b * XBUF + (l + 32) * ROWB) + q * 4;
        unsigned long long acc[2][12];
#pragma unroll
        for (int j = 0; j < 12; j++) { acc[0][j] = 0ull; acc[1][j] = 0ull; }
#pragma unroll
        for (int c4 = 0; c4 < 4; c4++) {
            float4 a0 = x0[c4];
            float4 a1 = x1[c4];
#pragma unroll
            for (int s = 0; s < 4; s++) {
                int k = (q << 4) + (c4 << 2) + s;
                unsigned long long xx0 = pack2(getc(a0, s));
                unsigned long long xx1 = pack2(getc(a1, s));
#pragma unroll
                for (int j = 0; j < 6; j++) {
                    ulonglong2 wv = swp[k * 6 + j];
                    acc[0][2 * j]     = ffma2(xx0, wv.x, acc[0][2 * j]);
                    acc[0][2 * j + 1] = ffma2(xx0, wv.y, acc[0][2 * j + 1]);
                    acc[1][2 * j]     = ffma2(xx1, wv.x, acc[1][2 * j]);
                    acc[1][2 * j + 1] = ffma2(xx1, wv.y, acc[1][2 * j + 1]);
                }
            }
        }
        __syncthreads();  // all x reads done; buffer b becomes scratch

        char* scratch = smem + b * XBUF;
        if (q >= 8) {
            unsigned long long* dst =
                (unsigned long long*)(scratch + ((q - 8) * 32 + l) * SLOT);
#pragma unroll
            for (int j = 0; j < 12; j++) { dst[j] = acc[0][j]; dst[12 + j] = acc[1][j]; }
        }
        __syncthreads();
        if (q < 8) {
            unsigned long long* src =
                (unsigned long long*)(scratch + (q * 32 + l) * SLOT);
#pragma unroll
            for (int j = 0; j < 12; j++) {
                acc[0][j] = addf2(acc[0][j], src[j]);
                acc[1][j] = addf2(acc[1][j], src[12 + j]);
            }
#pragma unroll
            for (int j = 0; j < 12; j++) { src[j] = acc[0][j]; src[12 + j] = acc[1][j]; }
        }
        __syncthreads();

        // final fold over q=0..7 + epilogue
        for (int s = t; s < 768; s += GE_TPB) {
            int pt = s & 63, j = s >> 6;  // j in [0,12)
            float lo = 0.f, hi = 0.f;
#pragma unroll
            for (int q2 = 0; q2 < 8; q2++) {
                unsigned long long pv = *(const unsigned long long*)(
                    scratch + (q2 * 32 + (pt & 31)) * SLOT + (pt >> 5) * 96 + j * 8);
                float a, bb;
                unpack2(pv, a, bb);
                lo += a; hi += bb;
            }
            if (pt < nv) {
                int col = j << 1;
                float2 o;
                if (col < 6) { o.x = __expf(sc * lo); o.y = __expf(sc * hi); }
                else         { o.x = lo + sb[col];    o.y = hi + sb[col + 1]; }
                *(float2*)(out + (size_t)sidx[b * 64 + pt] * 24 + col) = o;
            }
        }
        __syncthreads();  // buffer b free for the next refill
    }
}

extern "C" void kernel_launch(void* const* d_in, const int* in_sizes, int n_in,
                              void* d_out, int out_size) {
    const float* feats  = (const float*)d_in[0];
    const float* scores = (const float*)d_in[1];
    const float* w_reg  = (const float*)d_in[2];
    const float* w_cls  = (const float*)d_in[3];
    const float* b_cls  = (const float*)d_in[4];
    const float* scale  = (const float*)d_in[5];
    const int*   bids   = (const int*)d_in[6];
    const int*   nb     = (n_in > 7) ? (const int*)d_in[7] : nullptr;
    const int*   kp     = (n_in > 8) ? (const int*)d_in[8] : nullptr;
    int N = in_sizes[0] / 256;

    static bool attr_set = false;
    if (!attr_set) {
        cudaFuncSetAttribute(gemv_kernel,
                             cudaFuncAttributeMaxDynamicSharedMemorySize, SMEM_TOT);
        attr_set = true;
    }

    sel_kernel<<<SEL_NCTA, SEL_TPB>>>(scores, bids, b_cls, nb, kp,
                                      (float4*)d_out, N);
    gemv_kernel<<<GE_NCTA, GE_TPB, SMEM_TOT>>>(feats, w_reg, w_cls, b_cls,
                                               scale, (float*)d_out);
}

// round 10
// speedup vs baseline: 1.1325x; 1.0284x over previous
#include <cuda_runtime.h>
#include <cstdint>
#include <math.h>

#define NBIN 65536
#define MAXB 16
#define NMAX 262144
#define ZN (MAXB * NBIN / 4)

#define SEL_TPB 1024
#define SEL_NCTA 296

#define GE_TPB 512
#define GE_NCTA 148
#define ROWB 1040                    // 260 words: conflict-free x LDS.128
#define XBUF (64 * ROWB)             // 66560
#define SLOT 208                     // stride 13x16B: phase pattern conflict-free
#define SW_OFF (2 * XBUF)            // 133120
#define SIDX_OFF (SW_OFF + 24576)    // 157696
#define SB_OFF (SIDX_OFF + 512)      // 158208
#define MBAR_OFF (SB_OFF + 96)       // 158304
#define SMEM_TOT (MBAR_OFF + 32)

// ---- device scratch (zero-init; every run restores zero state) ----
__device__ unsigned g_hist1[MAXB * NBIN];
__device__ unsigned g_hist2[MAXB * NBIN];
__device__ unsigned g_chunk1[MAXB * 256];
__device__ unsigned g_chunk2[MAXB * 256];
__device__ unsigned g_bucket1[MAXB];
__device__ unsigned g_rank1[MAXB];
__device__ unsigned g_kthkey[MAXB];
__device__ int g_list[NMAX];
__device__ int g_cnt;
__device__ unsigned g_bar[8];        // monotonic barrier counters (never reset)

__device__ __forceinline__ unsigned f2key(float s) {
    unsigned u = __float_as_uint(s);
    return (u & 0x80000000u) ? ~u : (u | 0x80000000u);
}
__device__ __forceinline__ unsigned long long ffma2(
    unsigned long long a, unsigned long long b, unsigned long long c) {
    unsigned long long d;
    asm("fma.rn.f32x2 %0, %1, %2, %3;" : "=l"(d) : "l"(a), "l"(b), "l"(c));
    return d;
}
__device__ __forceinline__ unsigned long long addf2(
    unsigned long long a, unsigned long long b) {
    unsigned long long d;
    asm("add.rn.f32x2 %0, %1, %2;" : "=l"(d) : "l"(a), "l"(b));
    return d;
}
__device__ __forceinline__ unsigned long long pack2(float x) {
    unsigned long long d;
    asm("mov.b64 %0, {%1, %1};" : "=l"(d) : "f"(x));
    return d;
}
__device__ __forceinline__ void unpack2(unsigned long long v, float& lo, float& hi) {
    asm("mov.b64 {%0, %1}, %2;" : "=f"(lo), "=f"(hi) : "l"(v));
}
__device__ __forceinline__ float getc(const float4& v, int s) {
    return (s == 0) ? v.x : (s == 1) ? v.y : (s == 2) ? v.z : v.w;
}
__device__ __forceinline__ uint32_t s2u(const void* p) {
    uint32_t a;
    asm("{ .reg .u64 t; cvta.to.shared.u64 t, %1; cvt.u32.u64 %0, t; }"
        : "=r"(a) : "l"(p));
    return a;
}
__device__ __forceinline__ void mbar_init(uint32_t mbar, uint32_t cnt) {
    asm volatile("mbarrier.init.shared.b64 [%0], %1;" :: "r"(mbar), "r"(cnt) : "memory");
}
__device__ __forceinline__ void mbar_expect(uint32_t mbar, uint32_t bytes) {
    asm volatile("mbarrier.arrive.expect_tx.shared.b64 _, [%0], %1;"
                 :: "r"(mbar), "r"(bytes) : "memory");
}
__device__ __forceinline__ void mbar_wait(uint32_t mbar, uint32_t parity) {
    asm volatile(
        "{\n\t.reg .pred P;\n"
        "WL_%=:\n\t"
        "mbarrier.try_wait.parity.acquire.cta.shared::cta.b64 P, [%0], %1, 0x989680;\n\t"
        "@P bra.uni WD_%=;\n\t"
        "bra.uni WL_%=;\n"
        "WD_%=:\n\t}"
        :: "r"(mbar), "r"(parity) : "memory");
}
__device__ __forceinline__ void bulk_copy(uint32_t dst, const void* src,
                                          uint32_t bytes, uint32_t mbar) {
    asm volatile(
        "cp.async.bulk.shared::cluster.global.mbarrier::complete_tx::bytes "
        "[%0], [%1], %2, [%3];"
        :: "r"(dst), "l"(src), "r"(bytes), "r"(mbar) : "memory");
}

// Reset-free grid barrier (SEL_NCTA CTAs, all co-resident).
__device__ __forceinline__ void gbar(int i) {
    __syncthreads();
    if (threadIdx.x == 0) {
        __threadfence();
        unsigned old = atomicAdd(&g_bar[i], 1u);
        unsigned target = old - (old % SEL_NCTA) + SEL_NCTA;
        unsigned cur;
        do {
            asm volatile("ld.acquire.gpu.global.u32 %0, [%1];"
                         : "=r"(cur) : "l"(&g_bar[i]) : "memory");
        } while ((int)(cur - target) < 0);
    }
    __syncthreads();
}

// CTA b handles batch b; threads 0..255 active; two shfl suffix scans.
__device__ void scan_phase(int level, int b, unsigned target,
                           unsigned* wsum, int* s_sel, unsigned* s_rem) {
    const unsigned* h  = (level == 1 ? g_hist1  : g_hist2)  + (size_t)b * NBIN;
    const unsigned* ch = (level == 1 ? g_chunk1 : g_chunk2) + (size_t)b * 256;

    int t = threadIdx.x, lane = t & 31, w = t >> 5;
    unsigned v = 0, x = 0;

    if (t < 256) {
        v = ch[t];
        x = v;
#pragma unroll
        for (int off = 1; off < 32; off <<= 1) {
            unsigned nv = __shfl_down_sync(0xffffffffu, x, off);
            if (lane + off < 32) x += nv;
        }
        if (lane == 0) wsum[w] = x;
    }
    __syncthreads();
    if (t < 256) {
        unsigned add = 0;
        for (int w2 = w + 1; w2 < 8; w2++) add += wsum[w2];
        unsigned s = x + add;
        if (s >= target && s - v < target) { *s_sel = t; *s_rem = target - (s - v); }
    }
    __syncthreads();
    int sel = *s_sel;
    unsigned rem = *s_rem;
    __syncthreads();

    if (t < 256) {
        v = h[sel * 256 + t];
        x = v;
#pragma unroll
        for (int off = 1; off < 32; off <<= 1) {
            unsigned nv = __shfl_down_sync(0xffffffffu, x, off);
            if (lane + off < 32) x += nv;
        }
        if (lane == 0) wsum[w] = x;
    }
    __syncthreads();
    if (t < 256) {
        unsigned add = 0;
        for (int w2 = w + 1; w2 < 8; w2++) add += wsum[w2];
        unsigned s = x + add;
        if (s >= rem && s - v < rem) {
            unsigned bin = (unsigned)(sel * 256 + t);
            if (level == 1) {
                g_bucket1[b] = bin;
                g_rank1[b] = rem - (s - v);
            } else {
                g_kthkey[b] = (g_bucket1[b] << 16) | bin;
            }
        }
    }
}

// Fused selection: hist1 -> scan1 -> hist2 -> scan2 -> compact/fill.
__global__ void __launch_bounds__(SEL_TPB, 2) sel_kernel(
    const float* __restrict__ scores,
    const int* __restrict__ bids,
    const float* __restrict__ b_cls,
    const int* __restrict__ nb_ptr,
    const int* __restrict__ k_ptr,
    float4* __restrict__ out4, int N) {
    __shared__ unsigned wsum[8];
    __shared__ int s_sel;
    __shared__ unsigned s_rem;
    __shared__ float sbq[24];
    __shared__ unsigned skey[MAXB];
    __shared__ int warp_cnt[32];
    __shared__ int warp_off[32];
    __shared__ int cta_base;

    int t = threadIdx.x;
    int bid = blockIdx.x;
    int gid = bid * SEL_TPB + t;

    int B = nb_ptr ? *nb_ptr : 8;
    if (B < 1 || B > MAXB) B = 8;
    unsigned K = (unsigned)(k_ptr ? *k_ptr : 8192);

    // P1: hist1 + chunk1
    if (gid < N) {
        unsigned b = (unsigned)bids[gid];
        if (b < (unsigned)MAXB) {
            unsigned key = f2key(scores[gid]);
            atomicAdd(&g_hist1[b * NBIN + (key >> 16)], 1u);
            atomicAdd(&g_chunk1[b * 256 + (key >> 24)], 1u);
        }
    }
    gbar(0);

    // P2: scan level 1
    if (bid < B) scan_phase(1, bid, K, wsum, &s_sel, &s_rem);
    gbar(1);

    // P3: hist2 + chunk2; zero level-1 state
    if (gid < ZN) reinterpret_cast<uint4*>(g_hist1)[gid] = make_uint4(0u, 0u, 0u, 0u);
    if (gid < MAXB * 256) g_chunk1[gid] = 0u;
    if (gid < N) {
        unsigned b = (unsigned)bids[gid];
        if (b < (unsigned)MAXB) {
            unsigned key = f2key(scores[gid]);
            if ((key >> 16) == g_bucket1[b]) {
                atomicAdd(&g_hist2[b * NBIN + (key & 0xFFFFu)], 1u);
                atomicAdd(&g_chunk2[b * 256 + ((key >> 8) & 0xFFu)], 1u);
            }
        }
    }
    gbar(2);

    // P4: scan level 2 + reset g_cnt
    if (bid == 0 && t == 0) g_cnt = 0;
    if (bid < B) scan_phase(2, bid, g_rank1[bid], wsum, &s_sel, &s_rem);
    gbar(3);

    // P5: compact (CTA-aggregated g_cnt atomic) + fill; zero level-2 state
    if (t < MAXB) skey[t] = g_kthkey[t];
    if (t < 24) sbq[t] = (t < 6) ? 1.0f : b_cls[t - 6];
    __syncthreads();

    if (gid < ZN) reinterpret_cast<uint4*>(g_hist2)[gid] = make_uint4(0u, 0u, 0u, 0u);
    if (gid < MAXB * 256) g_chunk2[gid] = 0u;

    bool keep = false;
    if (gid < N) {
        unsigned b = (unsigned)bids[gid];
        unsigned key = f2key(scores[gid]);
        keep = (b < (unsigned)MAXB) && (key >= skey[b]);
        if (!keep) {
            float4* o = out4 + (size_t)gid * 6;
            o[0] = make_float4(1.f, 1.f, 1.f, 1.f);
            o[1] = make_float4(1.f, 1.f, sbq[6], sbq[7]);
            o[2] = make_float4(sbq[8], sbq[9], sbq[10], sbq[11]);
            o[3] = make_float4(sbq[12], sbq[13], sbq[14], sbq[15]);
            o[4] = make_float4(sbq[16], sbq[17], sbq[18], sbq[19]);
            o[5] = make_float4(sbq[20], sbq[21], sbq[22], sbq[23]);
        }
    }
    int lane = t & 31, w = t >> 5;
    unsigned bal = __ballot_sync(0xffffffffu, keep);
    int nk = __popc(bal);
    if (lane == 0) warp_cnt[w] = nk;
    __syncthreads();
    if (t < 32) {
        int v = warp_cnt[t];
        int inc = v;
#pragma unroll
        for (int o = 1; o < 32; o <<= 1) {
            int n = __shfl_up_sync(0xffffffffu, inc, o);
            if (t >= o) inc += n;
        }
        warp_off[t] = inc - v;
        if (t == 31) cta_base = atomicAdd(&g_cnt, inc);
    }
    __syncthreads();
    if (keep)
        g_list[cta_base + warp_off[w] + __popc(bal & ((1u << lane) - 1u))] = gid;
}

// Staged GEMV (R8-proven): tile=64 pts, 512 thr. lane l owns pts (l, l+32);
// warp q owns k-slice [16q,16q+16). Double-buffered cp.async.bulk; two-phase
// smem K-fold (only warps q>=8 store in phase 1: 256 slots x 208 B <= XBUF).
__global__ void __launch_bounds__(GE_TPB, 1) gemv_kernel(
    const float* __restrict__ feats,
    const float* __restrict__ w_reg,
    const float* __restrict__ w_cls,
    const float* __restrict__ b_cls,
    const float* __restrict__ scale,
    float* __restrict__ out) {
    extern __shared__ char smem[];
    float* sw = (float*)(smem + SW_OFF);    // [256][24]
    int* sidx = (int*)(smem + SIDX_OFF);    // [2][64]
    float* sb = (float*)(smem + SB_OFF);
    uint32_t mb0 = s2u(smem + MBAR_OFF);
    uint32_t mb1 = mb0 + 8;

    int t = threadIdx.x;
    int l = t & 31, q = t >> 5;             // q in [0,16)

    if (t < 24) sb[t] = (t < 6) ? 1.0f : b_cls[t - 6];
    for (int i = t; i < 6144; i += GE_TPB) {
        int k = i / 24, j = i % 24;
        sw[i] = (j < 6) ? w_reg[k * 6 + j] : w_cls[k * 18 + (j - 6)];
    }
    if (t < 2) mbar_init(t == 0 ? mb0 : mb1, 1);
    float sc = scale[0];
    int T = g_cnt;
    int ntiles = (T + 63) >> 6;
    __syncthreads();

    int tile = blockIdx.x;
    int ph0 = 0, ph1 = 0;

    if (tile < ntiles) {
        int nv = min(64, T - (tile << 6));
        if (t < 64) sidx[t] = (t < nv) ? g_list[(tile << 6) + t] : 0;
        if (t == 0) mbar_expect(mb0, (unsigned)nv << 10);
    }
    __syncthreads();
    if (tile < ntiles && t < min(64, T - (tile << 6)))
        bulk_copy(s2u(smem) + t * ROWB, feats + (size_t)sidx[t] * 256, 1024, mb0);

    const ulonglong2* swp = (const ulonglong2*)sw;  // 6 per k
    int b = 0;
    for (; tile < ntiles; tile += GE_NCTA, b ^= 1) {
        int nv = min(64, T - (tile << 6));
        int nxt = tile + GE_NCTA;
        int bn = b ^ 1;
        uint32_t mbn = bn ? mb1 : mb0;

        if (nxt < ntiles) {
            int nv2 = min(64, T - (nxt << 6));
            if (t < 64) sidx[bn * 64 + t] = (t < nv2) ? g_list[(nxt << 6) + t] : 0;
            if (t == 0) mbar_expect(mbn, (unsigned)nv2 << 10);
        }
        __syncthreads();
        if (nxt < ntiles) {
            int nv2 = min(64, T - (nxt << 6));
            if (t < nv2)
                bulk_copy(s2u(smem) + bn * XBUF + t * ROWB,
                          feats + (size_t)sidx[bn * 64 + t] * 256, 1024, mbn);
        }

        if (b == 0) { mbar_wait(mb0, ph0); ph0 ^= 1; }
        else        { mbar_wait(mb1, ph1); ph1 ^= 1; }

        // compute: 2 points (l, l+32), k-slice [16q, 16q+16)
        const float4* x0 = (const float4*)(smem + b * XBUF + l * ROWB) + q * 4;
        const float4* x1 = (const float4*)(smem + b * XBUF + (l + 32) * ROWB) + q * 4;
        unsigned long long acc[2][12];
#pragma unroll
        for (int j = 0; j < 12; j++) { acc[0][j] = 0ull; acc[1][j] = 0ull; }
#pragma unroll
        for (int c4 = 0; c4 < 4; c4++) {
            float4 a0 = x0[c4];
            float4 a1 = x1[c4];
#pragma unroll
            for (int s = 0; s < 4; s++) {
                int k = (q << 4) + (c4 << 2) + s;
                unsigned long long xx0 = pack2(getc(a0, s));
                unsigned long long xx1 = pack2(getc(a1, s));
#pragma unroll
                for (int j = 0; j < 6; j++) {
                    ulonglong2 wv = swp[k * 6 + j];
                    acc[0][2 * j]     = ffma2(xx0, wv.x, acc[0][2 * j]);
                    acc[0][2 * j + 1] = ffma2(xx0, wv.y, acc[0][2 * j + 1]);
                    acc[1][2 * j]     = ffma2(xx1, wv.x, acc[1][2 * j]);
                    acc[1][2 * j + 1] = ffma2(xx1, wv.y, acc[1][2 * j + 1]);
                }
            }
        }
        __syncthreads();  // all x reads done; buffer b becomes scratch

        // phase 1: warps 8..15 store partials (256 slots x 208 B <= XBUF)
        char* scratch = smem + b * XBUF;
        if (q >= 8) {
            unsigned long long* dst =
                (unsigned long long*)(scratch + ((q - 8) * 32 + l) * SLOT);
#pragma unroll
            for (int j = 0; j < 12; j++) { dst[j] = acc[0][j]; dst[12 + j] = acc[1][j]; }
        }
        __syncthreads();
        // phase 2: warps 0..7 add their partials in place
        if (q < 8) {
            unsigned long long* src =
                (unsigned long long*)(scratch + (q * 32 + l) * SLOT);
#pragma unroll
            for (int j = 0; j < 12; j++) {
                acc[0][j] = addf2(acc[0][j], src[j]);
                acc[1][j] = addf2(acc[1][j], src[12 + j]);
            }
#pragma unroll
            for (int j = 0; j < 12; j++) { src[j] = acc[0][j]; src[12 + j] = acc[1][j]; }
        }
        __syncthreads();

        // epilogue: fold the remaining 8 partials per (point, output-pair)
        for (int s = t; s < 768; s += GE_TPB) {
            int pt = s & 63, j = s >> 6;  // j in [0,12)
            unsigned long long sum = 0ull;
#pragma unroll
            for (int q2 = 0; q2 < 8; q2++) {
                unsigned long long pv = *(const unsigned long long*)(
                    scratch + (q2 * 32 + (pt & 31)) * SLOT + (pt >> 5) * 96 + j * 8);
                sum = addf2(sum, pv);
            }
            if (pt < nv) {
                float lo, hi;
                unpack2(sum, lo, hi);
                int col = j << 1;
                float2 o;
                if (col < 6) { o.x = __expf(sc * lo); o.y = __expf(sc * hi); }
                else         { o.x = lo + sb[col];    o.y = hi + sb[col + 1]; }
                *(float2*)(out + (size_t)sidx[b * 64 + pt] * 24 + col) = o;
            }
        }
        __syncthreads();  // buffer b free for the next refill
    }
}

extern "C" void kernel_launch(void* const* d_in, const int* in_sizes, int n_in,
                              void* d_out, int out_size) {
    const float* feats  = (const float*)d_in[0];
    const float* scores = (const float*)d_in[1];
    const float* w_reg  = (const float*)d_in[2];
    const float* w_cls  = (const float*)d_in[3];
    const float* b_cls  = (const float*)d_in[4];
    const float* scale  = (const float*)d_in[5];
    const int*   bids   = (const int*)d_in[6];
    const int*   nb     = (n_in > 7) ? (const int*)d_in[7] : nullptr;
    const int*   kp     = (n_in > 8) ? (const int*)d_in[8] : nullptr;
    int N = in_sizes[0] / 256;

    static bool attr_set = false;
    if (!attr_set) {
        cudaFuncSetAttribute(gemv_kernel,
                             cudaFuncAttributeMaxDynamicSharedMemorySize, SMEM_TOT);
        attr_set = true;
    }

    sel_kernel<<<SEL_NCTA, SEL_TPB>>>(scores, bids, b_cls, nb, kp,
                                      (float4*)d_out, N);
    gemv_kernel<<<GE_NCTA, GE_TPB, SMEM_TOT>>>(feats, w_reg, w_cls, b_cls,
                                               scale, (float*)d_out);
}

// round 11
// speedup vs baseline: 1.2379x; 1.0930x over previous
#include <cuda_runtime.h>
#include <cstdint>
#include <math.h>

#define NBIN 65536
#define MAXB 16
#define NMAX 262144
#define ZN (MAXB * NBIN / 4)

#define SEL_TPB 1024
#define SEL_NCTA 296

#define GE_TPB 512
#define GE_NCTA 148
#define ROWB 1040                    // 260 words: conflict-free x LDS.128
#define XBUF (64 * ROWB)             // 66560
#define SLOT 112                     // 28 words/slot: conflict-free fold phases
#define SW_OFF (2 * XBUF)            // 133120
#define SIDX_OFF (SW_OFF + 24576)    // 157696
#define SB_OFF (SIDX_OFF + 512)      // 158208
#define MBAR_OFF (SB_OFF + 96)       // 158304
#define SMEM_TOT (MBAR_OFF + 32)

// ---- device scratch (zero-init; every run restores zero state) ----
__device__ unsigned g_hist1[MAXB * NBIN];
__device__ unsigned g_hist2[MAXB * NBIN];
__device__ unsigned g_chunk1[MAXB * 256];
__device__ unsigned g_chunk2[MAXB * 256];
__device__ unsigned g_bucket1[MAXB];
__device__ unsigned g_rank1[MAXB];
__device__ unsigned g_kthkey[MAXB];
__device__ int g_list[NMAX];
__device__ int g_cnt;
__device__ unsigned g_bar[8];        // monotonic barrier counters (never reset)

__device__ __forceinline__ unsigned f2key(float s) {
    unsigned u = __float_as_uint(s);
    return (u & 0x80000000u) ? ~u : (u | 0x80000000u);
}
__device__ __forceinline__ unsigned long long ffma2(
    unsigned long long a, unsigned long long b, unsigned long long c) {
    unsigned long long d;
    asm("fma.rn.f32x2 %0, %1, %2, %3;" : "=l"(d) : "l"(a), "l"(b), "l"(c));
    return d;
}
__device__ __forceinline__ unsigned long long addf2(
    unsigned long long a, unsigned long long b) {
    unsigned long long d;
    asm("add.rn.f32x2 %0, %1, %2;" : "=l"(d) : "l"(a), "l"(b));
    return d;
}
__device__ __forceinline__ unsigned long long pack2(float x) {
    unsigned long long d;
    asm("mov.b64 %0, {%1, %1};" : "=l"(d) : "f"(x));
    return d;
}
__device__ __forceinline__ void unpack2(unsigned long long v, float& lo, float& hi) {
    asm("mov.b64 {%0, %1}, %2;" : "=f"(lo), "=f"(hi) : "l"(v));
}
__device__ __forceinline__ float getc(const float4& v, int s) {
    return (s == 0) ? v.x : (s == 1) ? v.y : (s == 2) ? v.z : v.w;
}
__device__ __forceinline__ uint32_t s2u(const void* p) {
    uint32_t a;
    asm("{ .reg .u64 t; cvta.to.shared.u64 t, %1; cvt.u32.u64 %0, t; }"
        : "=r"(a) : "l"(p));
    return a;
}
__device__ __forceinline__ void mbar_init(uint32_t mbar, uint32_t cnt) {
    asm volatile("mbarrier.init.shared.b64 [%0], %1;" :: "r"(mbar), "r"(cnt) : "memory");
}
__device__ __forceinline__ void mbar_expect(uint32_t mbar, uint32_t bytes) {
    asm volatile("mbarrier.arrive.expect_tx.shared.b64 _, [%0], %1;"
                 :: "r"(mbar), "r"(bytes) : "memory");
}
__device__ __forceinline__ void mbar_wait(uint32_t mbar, uint32_t parity) {
    asm volatile(
        "{\n\t.reg .pred P;\n"
        "WL_%=:\n\t"
        "mbarrier.try_wait.parity.acquire.cta.shared::cta.b64 P, [%0], %1, 0x989680;\n\t"
        "@P bra.uni WD_%=;\n\t"
        "bra.uni WL_%=;\n"
        "WD_%=:\n\t}"
        :: "r"(mbar), "r"(parity) : "memory");
}
__device__ __forceinline__ void bulk_copy(uint32_t dst, const void* src,
                                          uint32_t bytes, uint32_t mbar) {
    asm volatile(
        "cp.async.bulk.shared::cluster.global.mbarrier::complete_tx::bytes "
        "[%0], [%1], %2, [%3];"
        :: "r"(dst), "l"(src), "r"(bytes), "r"(mbar) : "memory");
}

// Reset-free grid barrier (SEL_NCTA CTAs, all co-resident).
__device__ __forceinline__ void gbar(int i) {
    __syncthreads();
    if (threadIdx.x == 0) {
        __threadfence();
        unsigned old = atomicAdd(&g_bar[i], 1u);
        unsigned target = old - (old % SEL_NCTA) + SEL_NCTA;
        unsigned cur;
        do {
            asm volatile("ld.acquire.gpu.global.u32 %0, [%1];"
                         : "=r"(cur) : "l"(&g_bar[i]) : "memory");
        } while ((int)(cur - target) < 0);
    }
    __syncthreads();
}

// CTA b handles batch b; threads 0..255 active; two shfl suffix scans.
__device__ void scan_phase(int level, int b, unsigned target,
                           unsigned* wsum, int* s_sel, unsigned* s_rem) {
    const unsigned* h  = (level == 1 ? g_hist1  : g_hist2)  + (size_t)b * NBIN;
    const unsigned* ch = (level == 1 ? g_chunk1 : g_chunk2) + (size_t)b * 256;

    int t = threadIdx.x, lane = t & 31, w = t >> 5;
    unsigned v = 0, x = 0;

    if (t < 256) {
        v = ch[t];
        x = v;
#pragma unroll
        for (int off = 1; off < 32; off <<= 1) {
            unsigned nv = __shfl_down_sync(0xffffffffu, x, off);
            if (lane + off < 32) x += nv;
        }
        if (lane == 0) wsum[w] = x;
    }
    __syncthreads();
    if (t < 256) {
        unsigned add = 0;
        for (int w2 = w + 1; w2 < 8; w2++) add += wsum[w2];
        unsigned s = x + add;
        if (s >= target && s - v < target) { *s_sel = t; *s_rem = target - (s - v); }
    }
    __syncthreads();
    int sel = *s_sel;
    unsigned rem = *s_rem;
    __syncthreads();

    if (t < 256) {
        v = h[sel * 256 + t];
        x = v;
#pragma unroll
        for (int off = 1; off < 32; off <<= 1) {
            unsigned nv = __shfl_down_sync(0xffffffffu, x, off);
            if (lane + off < 32) x += nv;
        }
        if (lane == 0) wsum[w] = x;
    }
    __syncthreads();
    if (t < 256) {
        unsigned add = 0;
        for (int w2 = w + 1; w2 < 8; w2++) add += wsum[w2];
        unsigned s = x + add;
        if (s >= rem && s - v < rem) {
            unsigned bin = (unsigned)(sel * 256 + t);
            if (level == 1) {
                g_bucket1[b] = bin;
                g_rank1[b] = rem - (s - v);
            } else {
                g_kthkey[b] = (g_bucket1[b] << 16) | bin;
            }
        }
    }
}

// Fused selection: hist1 -> scan1 -> hist2 -> scan2 -> compact/fill.
__global__ void __launch_bounds__(SEL_TPB, 2) sel_kernel(
    const float* __restrict__ scores,
    const int* __restrict__ bids,
    const float* __restrict__ b_cls,
    const int* __restrict__ nb_ptr,
    const int* __restrict__ k_ptr,
    float4* __restrict__ out4, int N) {
    __shared__ unsigned wsum[8];
    __shared__ int s_sel;
    __shared__ unsigned s_rem;
    __shared__ float sbq[24];
    __shared__ unsigned skey[MAXB];
    __shared__ int warp_cnt[32];
    __shared__ int warp_off[32];
    __shared__ int cta_base;

    int t = threadIdx.x;
    int bid = blockIdx.x;
    int gid = bid * SEL_TPB + t;

    int B = nb_ptr ? *nb_ptr : 8;
    if (B < 1 || B > MAXB) B = 8;
    unsigned K = (unsigned)(k_ptr ? *k_ptr : 8192);

    // P1: hist1 + chunk1
    if (gid < N) {
        unsigned b = (unsigned)bids[gid];
        if (b < (unsigned)MAXB) {
            unsigned key = f2key(scores[gid]);
            atomicAdd(&g_hist1[b * NBIN + (key >> 16)], 1u);
            atomicAdd(&g_chunk1[b * 256 + (key >> 24)], 1u);
        }
    }
    gbar(0);

    // P2: scan level 1
    if (bid < B) scan_phase(1, bid, K, wsum, &s_sel, &s_rem);
    gbar(1);

    // P3: hist2 + chunk2; zero level-1 state
    if (gid < ZN) reinterpret_cast<uint4*>(g_hist1)[gid] = make_uint4(0u, 0u, 0u, 0u);
    if (gid < MAXB * 256) g_chunk1[gid] = 0u;
    if (gid < N) {
        unsigned b = (unsigned)bids[gid];
        if (b < (unsigned)MAXB) {
            unsigned key = f2key(scores[gid]);
            if ((key >> 16) == g_bucket1[b]) {
                atomicAdd(&g_hist2[b * NBIN + (key & 0xFFFFu)], 1u);
                atomicAdd(&g_chunk2[b * 256 + ((key >> 8) & 0xFFu)], 1u);
            }
        }
    }
    gbar(2);

    // P4: scan level 2 + reset g_cnt
    if (bid == 0 && t == 0) g_cnt = 0;
    if (bid < B) scan_phase(2, bid, g_rank1[bid], wsum, &s_sel, &s_rem);
    gbar(3);

    // P5: compact (CTA-aggregated g_cnt atomic) + fill; zero level-2 state
    if (t < MAXB) skey[t] = g_kthkey[t];
    if (t < 24) sbq[t] = (t < 6) ? 1.0f : b_cls[t - 6];
    __syncthreads();

    if (gid < ZN) reinterpret_cast<uint4*>(g_hist2)[gid] = make_uint4(0u, 0u, 0u, 0u);
    if (gid < MAXB * 256) g_chunk2[gid] = 0u;

    bool keep = false;
    if (gid < N) {
        unsigned b = (unsigned)bids[gid];
        unsigned key = f2key(scores[gid]);
        keep = (b < (unsigned)MAXB) && (key >= skey[b]);
        if (!keep) {
            float4* o = out4 + (size_t)gid * 6;
            o[0] = make_float4(1.f, 1.f, 1.f, 1.f);
            o[1] = make_float4(1.f, 1.f, sbq[6], sbq[7]);
            o[2] = make_float4(sbq[8], sbq[9], sbq[10], sbq[11]);
            o[3] = make_float4(sbq[12], sbq[13], sbq[14], sbq[15]);
            o[4] = make_float4(sbq[16], sbq[17], sbq[18], sbq[19]);
            o[5] = make_float4(sbq[20], sbq[21], sbq[22], sbq[23]);
        }
    }
    int lane = t & 31, w = t >> 5;
    unsigned bal = __ballot_sync(0xffffffffu, keep);
    int nk = __popc(bal);
    if (lane == 0) warp_cnt[w] = nk;
    __syncthreads();
    if (t < 32) {
        int v = warp_cnt[t];
        int inc = v;
#pragma unroll
        for (int o = 1; o < 32; o <<= 1) {
            int n = __shfl_up_sync(0xffffffffu, inc, o);
            if (t >= o) inc += n;
        }
        warp_off[t] = inc - v;
        if (t == 31) cta_base = atomicAdd(&g_cnt, inc);
    }
    __syncthreads();
    if (keep)
        g_list[cta_base + warp_off[w] + __popc(bal & ((1u << lane) - 1u))] = gid;
}

// Staged GEMV: tile=64 pts, 512 thr = 8 k-slices(32k) x 2 output-halves.
// Lane l owns pts (l, l+32); acc[2][6]. Weights/x prefetched one step ahead
// to cover LDS latency. Double-buffered cp.async.bulk; single-phase K-fold.
__global__ void __launch_bounds__(GE_TPB, 1) gemv_kernel(
    const float* __restrict__ feats,
    const float* __restrict__ w_reg,
    const float* __restrict__ w_cls,
    const float* __restrict__ b_cls,
    const float* __restrict__ scale,
    float* __restrict__ out) {
    extern __shared__ char smem[];
    float* sw = (float*)(smem + SW_OFF);    // [256][24]
    int* sidx = (int*)(smem + SIDX_OFF);    // [2][64]
    float* sb = (float*)(smem + SB_OFF);
    uint32_t mb0 = s2u(smem + MBAR_OFF);
    uint32_t mb1 = mb0 + 8;

    int t = threadIdx.x;
    int l = t & 31, wid = t >> 5;
    int q = wid & 7;                 // k-slice [32q, 32q+32)
    int jh = wid >> 3;               // output half: floats [12jh, 12jh+12)

    if (t < 24) sb[t] = (t < 6) ? 1.0f : b_cls[t - 6];
    for (int i = t; i < 6144; i += GE_TPB) {
        int k = i / 24, j = i % 24;
        sw[i] = (j < 6) ? w_reg[k * 6 + j] : w_cls[k * 18 + (j - 6)];
    }
    if (t < 2) mbar_init(t == 0 ? mb0 : mb1, 1);
    float sc = scale[0];
    int T = g_cnt;
    int ntiles = (T + 63) >> 6;
    __syncthreads();

    int tile = blockIdx.x;
    int ph0 = 0, ph1 = 0;

    if (tile < ntiles) {
        int nv = min(64, T - (tile << 6));
        if (t < 64) sidx[t] = (t < nv) ? g_list[(tile << 6) + t] : 0;
        if (t == 0) mbar_expect(mb0, (unsigned)nv << 10);
    }
    __syncthreads();
    if (tile < ntiles && t < min(64, T - (tile << 6)))
        bulk_copy(s2u(smem) + t * ROWB, feats + (size_t)sidx[t] * 256, 1024, mb0);

    // per-(q,jh) weight base: k-stride = 96B = 6 ulonglong2
    const ulonglong2* wp = (const ulonglong2*)(sw + q * 768 + jh * 12);

    int b = 0;
    for (; tile < ntiles; tile += GE_NCTA, b ^= 1) {
        int nv = min(64, T - (tile << 6));
        int nxt = tile + GE_NCTA;
        int bn = b ^ 1;
        uint32_t mbn = bn ? mb1 : mb0;

        if (nxt < ntiles) {
            int nv2 = min(64, T - (nxt << 6));
            if (t < 64) sidx[bn * 64 + t] = (t < nv2) ? g_list[(nxt << 6) + t] : 0;
            if (t == 0) mbar_expect(mbn, (unsigned)nv2 << 10);
        }
        __syncthreads();
        if (nxt < ntiles) {
            int nv2 = min(64, T - (nxt << 6));
            if (t < nv2)
                bulk_copy(s2u(smem) + bn * XBUF + t * ROWB,
                          feats + (size_t)sidx[bn * 64 + t] * 256, 1024, mbn);
        }

        if (b == 0) { mbar_wait(mb0, ph0); ph0 ^= 1; }
        else        { mbar_wait(mb1, ph1); ph1 ^= 1; }

        // compute: pts (l, l+32), k in [32q,32q+32), output pairs [6jh,6jh+6)
        const float4* x0 = (const float4*)(smem + b * XBUF + l * ROWB) + q * 8;
        const float4* x1 = (const float4*)(smem + b * XBUF + (l + 32) * ROWB) + q * 8;
        unsigned long long acc0[6], acc1[6];
#pragma unroll
        for (int j = 0; j < 6; j++) { acc0[j] = 0ull; acc1[j] = 0ull; }

        ulonglong2 wA0 = wp[0], wA1 = wp[1], wA2 = wp[2];  // k = 32q
        float4 a0 = x0[0], a1 = x1[0];
#pragma unroll
        for (int c4 = 0; c4 < 8; c4++) {
            float4 n0, n1;
            if (c4 < 7) { n0 = x0[c4 + 1]; n1 = x1[c4 + 1]; }
#pragma unroll
            for (int s = 0; s < 4; s++) {
                ulonglong2 w0 = wA0, w1 = wA1, w2 = wA2;
                int kn = c4 * 4 + s + 1;
                if (kn < 32) {
                    const ulonglong2* wn = wp + kn * 6;
                    wA0 = wn[0]; wA1 = wn[1]; wA2 = wn[2];
                }
                unsigned long long xx0 = pack2(getc(a0, s));
                unsigned long long xx1 = pack2(getc(a1, s));
                acc0[0] = ffma2(xx0, w0.x, acc0[0]);
                acc0[1] = ffma2(xx0, w0.y, acc0[1]);
                acc0[2] = ffma2(xx0, w1.x, acc0[2]);
                acc0[3] = ffma2(xx0, w1.y, acc0[3]);
                acc0[4] = ffma2(xx0, w2.x, acc0[4]);
                acc0[5] = ffma2(xx0, w2.y, acc0[5]);
                acc1[0] = ffma2(xx1, w0.x, acc1[0]);
                acc1[1] = ffma2(xx1, w0.y, acc1[1]);
                acc1[2] = ffma2(xx1, w1.x, acc1[2]);
                acc1[3] = ffma2(xx1, w1.y, acc1[3]);
                acc1[4] = ffma2(xx1, w2.x, acc1[4]);
                acc1[5] = ffma2(xx1, w2.y, acc1[5]);
            }
            a0 = n0; a1 = n1;
        }
        __syncthreads();  // all x reads done; buffer b becomes scratch

        // single-phase fold store: slot (wid*32+l), 6 x STS.128
        // 512 slots x 112 B = 57344 <= XBUF; stride 28 words: conflict-free
        char* scratch = smem + b * XBUF;
        {
            ulonglong2* dst = (ulonglong2*)(scratch + (wid * 32 + l) * SLOT);
            dst[0] = make_ulonglong2(acc0[0], acc0[1]);
            dst[1] = make_ulonglong2(acc0[2], acc0[3]);
            dst[2] = make_ulonglong2(acc0[4], acc0[5]);
            dst[3] = make_ulonglong2(acc1[0], acc1[1]);
            dst[4] = make_ulonglong2(acc1[2], acc1[3]);
            dst[5] = make_ulonglong2(acc1[4], acc1[5]);
        }
        __syncthreads();

        // epilogue: fold 8 q-partials per (point, output-pair)
        for (int s = t; s < 768; s += GE_TPB) {
            int pt = s & 63, jj = s >> 6;       // jj in [0,12)
            int jh2 = jj / 6, j6 = jj % 6;
            unsigned long long sum = 0ull;
#pragma unroll
            for (int q2 = 0; q2 < 8; q2++) {
                unsigned long long pv = *(const unsigned long long*)(
                    scratch + ((jh2 * 8 + q2) * 32 + (pt & 31)) * SLOT +
                    (pt >> 5) * 48 + j6 * 8);
                sum = addf2(sum, pv);
            }
            if (pt < nv) {
                float lo, hi;
                unpack2(sum, lo, hi);
                int col = jh2 * 12 + j6 * 2;
                float2 o;
                if (col < 6) { o.x = __expf(sc * lo); o.y = __expf(sc * hi); }
                else         { o.x = lo + sb[col];    o.y = hi + sb[col + 1]; }
                *(float2*)(out + (size_t)sidx[b * 64 + pt] * 24 + col) = o;
            }
        }
        __syncthreads();  // buffer b free for the next refill
    }
}

extern "C" void kernel_launch(void* const* d_in, const int* in_sizes, int n_in,
                              void* d_out, int out_size) {
    const float* feats  = (const float*)d_in[0];
    const float* scores = (const float*)d_in[1];
    const float* w_reg  = (const float*)d_in[2];
    const float* w_cls  = (const float*)d_in[3];
    const float* b_cls  = (const float*)d_in[4];
    const float* scale  = (const float*)d_in[5];
    const int*   bids   = (const int*)d_in[6];
    const int*   nb     = (n_in > 7) ? (const int*)d_in[7] : nullptr;
    const int*   kp     = (n_in > 8) ? (const int*)d_in[8] : nullptr;
    int N = in_sizes[0] / 256;

    static bool attr_set = false;
    if (!attr_set) {
        cudaFuncSetAttribute(gemv_kernel,
                             cudaFuncAttributeMaxDynamicSharedMemorySize, SMEM_TOT);
        attr_set = true;
    }

    sel_kernel<<<SEL_NCTA, SEL_TPB>>>(scores, bids, b_cls, nb, kp,
                                      (float4*)d_out, N);
    gemv_kernel<<<GE_NCTA, GE_TPB, SMEM_TOT>>>(feats, w_reg, w_cls, b_cls,
                                               scale, (float*)d_out);
}